// round 12
// baseline (speedup 1.0000x reference)
#include <cuda_runtime.h>
#include <cuda_fp16.h>
#include <math.h>
#include <stdint.h>

#define NN 100000
#define EE 1600000
#define NW (NN*32)

// ---------------- device scratch (static, no allocation) ----------------
__device__ __align__(16) float g_feats[11][NW];
__device__ __align__(16) float g_preA[NW];        // init-layer pre-BN (fp32)
__device__ __align__(16) float g_preB[NW];        // update pre-BN (fp32)
__device__ __align__(16) __half g_msg16[NW];      // msg pre-BN rows (fp16)
__device__ __align__(16) float g_agg[NW];
__device__ float g_stats[22][64];
__device__ __align__(16) float g_scale[22][32];
__device__ __align__(16) float g_shift[22][32];
__device__ __align__(16) float g_h256[NN*256];
__device__ __align__(16) float g_h128[NN*128];
__device__ __align__(16) float g_h64[NN*64];
// pre-split tf32 weights for the final MLP (hi/lo)
__device__ uint32_t g_whi[51200];
__device__ uint32_t g_wlo[51200];
// CSR scratch
__device__ int g_deg[NN];
__device__ int g_cursor[NN];
__device__ int g_rowptr[NN+1];
__device__ int g_csrsrc[EE];

__device__ __forceinline__ float lrelu(float x){ return x > 0.f ? x : 0.01f*x; }

// ---------------- tf32 helpers (base ISA, sm_80+) ----------------
__device__ __forceinline__ uint32_t f2tf32(float x){
  uint32_t r; asm("cvt.rna.tf32.f32 %0, %1;" : "=r"(r) : "f"(x)); return r;
}
__device__ __forceinline__ void tf32_split(float x, uint32_t& hi, uint32_t& lo){
  uint32_t h = f2tf32(x);
  hi = h;
  lo = f2tf32(x - __uint_as_float(h));
}
__device__ __forceinline__ void mma_tf32(float* c, const uint32_t* a, const uint32_t* b){
  asm volatile("mma.sync.aligned.m16n8k8.row.col.f32.tf32.tf32.f32 "
    "{%0,%1,%2,%3}, {%4,%5,%6,%7}, {%8,%9}, {%0,%1,%2,%3};"
    : "+f"(c[0]), "+f"(c[1]), "+f"(c[2]), "+f"(c[3])
    : "r"(a[0]), "r"(a[1]), "r"(a[2]), "r"(a[3]), "r"(b[0]), "r"(b[1]));
}

// ---------------- weight pre-split (final MLP), single launch ----------------
__global__ void k_wsplit(const float* __restrict__ W0, const float* __restrict__ W1,
                         const float* __restrict__ W2, const float* __restrict__ W3){
  int i = blockIdx.x*blockDim.x + threadIdx.x;
  if (i >= 51200) return;
  float x;
  if (i < 8192)       x = W0[i];
  else if (i < 40960) x = W1[i - 8192];
  else if (i < 49152) x = W2[i - 40960];
  else                x = W3[i - 49152];
  uint32_t h = f2tf32(x);
  g_whi[i] = h;
  g_wlo[i] = f2tf32(x - __uint_as_float(h));
}

// ---------------- zero kernels ----------------
__global__ void k_zero_stats(){
  int i = blockIdx.x*blockDim.x + threadIdx.x;
  if (i < 22*64) ((float*)g_stats)[i] = 0.f;
  int stride = gridDim.x*blockDim.x;
  for (int j = i; j < NN; j += stride) g_deg[j] = 0;
}

// ---------------- CSR build ----------------
__global__ void k_count(const int* __restrict__ dst){
  int i = blockIdx.x*blockDim.x + threadIdx.x;
  if (i < EE) atomicAdd(&g_deg[dst[i]], 1);
}

__global__ void k_scan(){
  __shared__ int partial[1024];
  const int CH = 98;
  int t = threadIdx.x;
  int beg = t*CH, end = min(beg+CH, NN);
  int s = 0;
  for (int i = beg; i < end; i++) s += g_deg[i];
  partial[t] = s;
  __syncthreads();
  for (int off = 1; off < 1024; off <<= 1){
    int v = partial[t];
    int add = (t >= off) ? partial[t-off] : 0;
    __syncthreads();
    partial[t] = v + add;
    __syncthreads();
  }
  int run = (t > 0) ? partial[t-1] : 0;
  for (int i = beg; i < end; i++){
    g_rowptr[i] = run; g_cursor[i] = run;
    run += g_deg[i];
  }
  if (t == 1023) g_rowptr[NN] = partial[1023];
}

__global__ void k_fill(const int* __restrict__ src, const int* __restrict__ dst){
  int i = blockIdx.x*blockDim.x + threadIdx.x;
  if (i >= EE) return;
  int d = dst[i];
  int p = atomicAdd(&g_cursor[d], 1);
  g_csrsrc[p] = src[i];
}

// ---------------- per-block column-stat commit ----------------
__device__ __forceinline__ void stats_commit(float s, float sq, int slot){
  __shared__ float red[2][8][32];
  int c = threadIdx.x & 31, w = threadIdx.x >> 5;
  red[0][w][c] = s; red[1][w][c] = sq;
  __syncthreads();
  if (w == 0){
    float a = 0.f, b = 0.f;
#pragma unroll
    for (int j = 0; j < 8; j++){ a += red[0][j][c]; b += red[1][j][c]; }
    atomicAdd(&g_stats[slot][c],    a);
    atomicAdd(&g_stats[slot][32+c], b);
  }
}

// ---------------- init layer 0 ----------------
__global__ void k_init0(const float* __restrict__ x, const float* __restrict__ W0,
                        const float* __restrict__ b0){
  int c = threadIdx.x & 31;
  float wc = W0[c], bc = b0[c];
  float s = 0.f, sq = 0.f;
  int stride = gridDim.x*blockDim.x;
  for (int idx = blockIdx.x*blockDim.x + threadIdx.x; idx < NW; idx += stride){
    float v = fmaf(x[idx >> 5], wc, bc);
    g_preA[idx] = v; s += v; sq += v*v;
  }
  stats_commit(s, sq, 0);
}

// ---------------- finalize BN stats into fused scale/shift ----------------
__global__ void k_finalize(int slot, const float* __restrict__ g,
                           const float* __restrict__ be){
  int c = threadIdx.x;
  float m = g_stats[slot][c] * (1.f/NN);
  float v = g_stats[slot][32+c] * (1.f/NN) - m*m;
  float istd = rsqrtf(v + 1e-5f);
  float sc = g[c]*istd;
  g_scale[slot][c] = sc;
  g_shift[slot][c] = fmaf(-m, sc, be[c]);
}

// ---------------- register-weight small GEMM --------------------------------------
// OUT: 0 -> g_preA (fp32), 1 -> g_preB (fp32), 2 -> g_msg16 (fp16, msg layers)
template<int K, bool PRE, int OUT>
__global__ void __launch_bounds__(256) k_gemm2(int fidx, const float* __restrict__ Wg,
        const float* __restrict__ bias, int preslot, int outslot)
{
  __shared__ __align__(16) float in_sh[8][4][K];
  const float* in1 = PRE ? g_preA : g_feats[fidx];
  int lane = threadIdx.x & 31, w = threadIdx.x >> 5;
  float wreg[K];
#pragma unroll
  for (int k = 0; k < K; k++) wreg[k] = Wg[k*32 + lane];
  float b = bias[lane];
  float psc = 0.f, psh = 0.f;
  if (PRE){ psc = g_scale[preslot][lane]; psh = g_shift[preslot][lane]; }
  float s = 0.f, sq = 0.f;
  int gwarp  = blockIdx.x*8 + w;
  int nwarps = gridDim.x*8;
  for (int grp = gwarp; grp < NN/4; grp += nwarps){
    int r0 = grp*4;
#pragma unroll
    for (int j = 0; j < 4; j++){
      float v = in1[(r0+j)*32 + lane];
      if (PRE) v = lrelu(fmaf(v, psc, psh));
      in_sh[w][j][lane] = v;
      if (K == 64) in_sh[w][j][32 + lane] = g_agg[(r0+j)*32 + lane];
    }
    __syncwarp();
    float a0=b, a1=b, a2=b, a3=b;
#pragma unroll
    for (int k = 0; k < K; k += 4){
      float4 x0 = *(const float4*)&in_sh[w][0][k];
      float4 x1 = *(const float4*)&in_sh[w][1][k];
      float4 x2 = *(const float4*)&in_sh[w][2][k];
      float4 x3 = *(const float4*)&in_sh[w][3][k];
      a0 = fmaf(x0.x,wreg[k],a0); a0 = fmaf(x0.y,wreg[k+1],a0);
      a0 = fmaf(x0.z,wreg[k+2],a0); a0 = fmaf(x0.w,wreg[k+3],a0);
      a1 = fmaf(x1.x,wreg[k],a1); a1 = fmaf(x1.y,wreg[k+1],a1);
      a1 = fmaf(x1.z,wreg[k+2],a1); a1 = fmaf(x1.w,wreg[k+3],a1);
      a2 = fmaf(x2.x,wreg[k],a2); a2 = fmaf(x2.y,wreg[k+1],a2);
      a2 = fmaf(x2.z,wreg[k+2],a2); a2 = fmaf(x2.w,wreg[k+3],a2);
      a3 = fmaf(x3.x,wreg[k],a3); a3 = fmaf(x3.y,wreg[k+1],a3);
      a3 = fmaf(x3.z,wreg[k+2],a3); a3 = fmaf(x3.w,wreg[k+3],a3);
    }
    __syncwarp();
    if (OUT == 2){
      g_msg16[(r0+0)*32+lane] = __float2half(a0);
      g_msg16[(r0+1)*32+lane] = __float2half(a1);
      g_msg16[(r0+2)*32+lane] = __float2half(a2);
      g_msg16[(r0+3)*32+lane] = __float2half(a3);
    } else {
      float* out = (OUT == 1) ? g_preB : g_preA;
      out[(r0+0)*32+lane] = a0;
      out[(r0+1)*32+lane] = a1;
      out[(r0+2)*32+lane] = a2;
      out[(r0+3)*32+lane] = a3;
    }
    s  += a0+a1+a2+a3;
    sq += a0*a0+a1*a1+a2*a2+a3*a3;
  }
  stats_commit(s, sq, outslot);
}

// ---------------- CSR pull-gather (ILP-8, fp16 msg rows) ----------------
__global__ void __launch_bounds__(256) k_gather(int slot){
  int warp = (blockIdx.x*blockDim.x + threadIdx.x) >> 5;
  int lane = threadIdx.x & 31;
  if (warp >= NN) return;
  float sc = g_scale[slot][lane], sh = g_shift[slot][lane];
  int beg = g_rowptr[warp], end = g_rowptr[warp+1];
  float acc = 0.f;
  for (int base = beg; base < end; base += 32){
    int idx = base + lane;
    int s_l = (idx < end) ? g_csrsrc[idx] : 0;
    int nb = min(32, end - base);
    int j = 0;
    for (; j + 8 <= nb; j += 8){
      int s0 = __shfl_sync(0xffffffffu, s_l, j);
      int s1 = __shfl_sync(0xffffffffu, s_l, j+1);
      int s2 = __shfl_sync(0xffffffffu, s_l, j+2);
      int s3 = __shfl_sync(0xffffffffu, s_l, j+3);
      int s4 = __shfl_sync(0xffffffffu, s_l, j+4);
      int s5 = __shfl_sync(0xffffffffu, s_l, j+5);
      int s6 = __shfl_sync(0xffffffffu, s_l, j+6);
      int s7 = __shfl_sync(0xffffffffu, s_l, j+7);
      float v0 = __half2float(g_msg16[s0*32 + lane]);
      float v1 = __half2float(g_msg16[s1*32 + lane]);
      float v2 = __half2float(g_msg16[s2*32 + lane]);
      float v3 = __half2float(g_msg16[s3*32 + lane]);
      float v4 = __half2float(g_msg16[s4*32 + lane]);
      float v5 = __half2float(g_msg16[s5*32 + lane]);
      float v6 = __half2float(g_msg16[s6*32 + lane]);
      float v7 = __half2float(g_msg16[s7*32 + lane]);
      acc += lrelu(fmaf(v0, sc, sh));
      acc += lrelu(fmaf(v1, sc, sh));
      acc += lrelu(fmaf(v2, sc, sh));
      acc += lrelu(fmaf(v3, sc, sh));
      acc += lrelu(fmaf(v4, sc, sh));
      acc += lrelu(fmaf(v5, sc, sh));
      acc += lrelu(fmaf(v6, sc, sh));
      acc += lrelu(fmaf(v7, sc, sh));
    }
    for (; j < nb; j++){
      int ss = __shfl_sync(0xffffffffu, s_l, j);
      float v = __half2float(g_msg16[ss*32 + lane]);
      acc += lrelu(fmaf(v, sc, sh));
    }
  }
  g_agg[warp*32 + lane] = acc;
}

// ---------------- apply BN+lrelu (+residual) ----------------
__global__ void k_actstore(int slot, int ridx, int oidx){
  int c = threadIdx.x & 31;
  float sc = g_scale[slot][c], sh = g_shift[slot][c];
  const float* resid = (ridx >= 0) ? g_feats[ridx] : (const float*)0;
  float* dstp = g_feats[oidx];
  int stride = gridDim.x*blockDim.x;
  for (int i = blockIdx.x*blockDim.x + threadIdx.x; i < NW; i += stride){
    float v = lrelu(fmaf(g_preB[i], sc, sh));
    if (ridx >= 0) v += resid[i];
    dstp[i] = v;
  }
}

// ---------------- final MLP via mma.sync tf32 (3xTF32, pre-split W) ---------------
template<int L> struct FC;
template<> struct FC<0>{ static constexpr int K=32,  C=256, WOFF=0;     };
template<> struct FC<1>{ static constexpr int K=256, C=128, WOFF=8192;  };
template<> struct FC<2>{ static constexpr int K=128, C=64,  WOFF=40960; };
template<> struct FC<3>{ static constexpr int K=64,  C=32,  WOFF=49152; };

template<int L, bool HEAD>
__global__ void __launch_bounds__(256) k_fmma(const float* __restrict__ bias,
        const float* __restrict__ Wo, const float* __restrict__ bo,
        float* __restrict__ sig_out){
  constexpr int K = FC<L>::K, C = FC<L>::C, WOFF = FC<L>::WOFF;
  constexpr int NSUB = (C >= 64) ? 8 : C/8;
  const float* in = (L==0)? g_feats[10] : (L==1)? g_h256 : (L==2)? g_h128 : g_h64;
  float* out      = (L==0)? g_h256 : (L==1)? g_h128 : (L==2)? g_h64 : (float*)0;
  const uint32_t* WH = g_whi + WOFF;
  const uint32_t* WL = g_wlo + WOFF;
  __shared__ float wo_sh[32];
  if (HEAD){
    if (threadIdx.x < 32) wo_sh[threadIdx.x] = Wo[threadIdx.x];
    __syncthreads();
  }
  int lane = threadIdx.x & 31, w = threadIdx.x >> 5;
  int rowW = blockIdx.x*128 + w*16;
  int colW = blockIdx.y*(NSUB*8);
  int g = lane >> 2, tig = lane & 3;
  int r0 = rowW + g, r1 = r0 + 8;

  float acc[NSUB][4];
#pragma unroll
  for (int s = 0; s < NSUB; s++){
    acc[s][0] = 0.f; acc[s][1] = 0.f; acc[s][2] = 0.f; acc[s][3] = 0.f;
  }

  const float* inA0 = in + (size_t)r0*K;
  const float* inA1 = in + (size_t)r1*K;
  bool v0 = (r0 < NN), v1 = (r1 < NN);

#pragma unroll 2
  for (int k0 = 0; k0 < K; k0 += 8){
    int ka = k0 + tig;
    float x0 = v0 ? inA0[ka]     : 0.f;
    float x1 = v1 ? inA1[ka]     : 0.f;
    float x2 = v0 ? inA0[ka + 4] : 0.f;
    float x3 = v1 ? inA1[ka + 4] : 0.f;
    uint32_t aH[4], aL[4];
    tf32_split(x0, aH[0], aL[0]);
    tf32_split(x1, aH[1], aL[1]);
    tf32_split(x2, aH[2], aL[2]);
    tf32_split(x3, aH[3], aL[3]);

    uint32_t bH[NSUB][2], bL[NSUB][2];
#pragma unroll
    for (int s = 0; s < NSUB; s++){
      int col = colW + s*8 + g;
      size_t i0 = (size_t)ka*C + col;
      size_t i1 = (size_t)(ka+4)*C + col;
      bH[s][0] = WH[i0]; bL[s][0] = WL[i0];
      bH[s][1] = WH[i1]; bL[s][1] = WL[i1];
    }
#pragma unroll
    for (int s = 0; s < NSUB; s++){
      mma_tf32(acc[s], aH, bH[s]);
      mma_tf32(acc[s], aH, bL[s]);
      mma_tf32(acc[s], aL, bH[s]);
    }
  }

  if (!HEAD){
#pragma unroll
    for (int s = 0; s < NSUB; s++){
      int c0 = colW + s*8 + 2*tig;
      float b0 = bias[c0], b1 = bias[c0+1];
      if (v0){
        out[(size_t)r0*C + c0]     = lrelu(acc[s][0] + b0);
        out[(size_t)r0*C + c0 + 1] = lrelu(acc[s][1] + b1);
      }
      if (v1){
        out[(size_t)r1*C + c0]     = lrelu(acc[s][2] + b0);
        out[(size_t)r1*C + c0 + 1] = lrelu(acc[s][3] + b1);
      }
    }
  } else {
    float z0 = 0.f, z1 = 0.f;
#pragma unroll
    for (int s = 0; s < NSUB; s++){
      int c0 = colW + s*8 + 2*tig;
      float b0 = bias[c0], b1 = bias[c0+1];
      float w0 = wo_sh[c0], w1 = wo_sh[c0+1];
      z0 += lrelu(acc[s][0] + b0)*w0 + lrelu(acc[s][1] + b1)*w1;
      z1 += lrelu(acc[s][2] + b0)*w0 + lrelu(acc[s][3] + b1)*w1;
    }
    z0 += __shfl_xor_sync(0xffffffffu, z0, 1);
    z0 += __shfl_xor_sync(0xffffffffu, z0, 2);
    z1 += __shfl_xor_sync(0xffffffffu, z1, 1);
    z1 += __shfl_xor_sync(0xffffffffu, z1, 2);
    if (tig == 0){
      float bb = bo[0];
      if (v0) sig_out[r0] = 1.f/(1.f + expf(-(z0 + bb)));
      if (v1) sig_out[r1] = 1.f/(1.f + expf(-(z1 + bb)));
    }
  }
}

// ---------------- launch ----------------
extern "C" void kernel_launch(void* const* d_in, const int* in_sizes, int n_in,
                              void* d_out, int out_size){
  const float* x    = (const float*)d_in[0];
  const int*   col  = (const int*)d_in[1];
  const float* Wi0  = (const float*)d_in[2];
  const float* bi0  = (const float*)d_in[3];
  const float* gi0  = (const float*)d_in[4];
  const float* bei0 = (const float*)d_in[5];
  const float* Wi1  = (const float*)d_in[6];
  const float* bi1  = (const float*)d_in[7];
  const float* gi1  = (const float*)d_in[8];
  const float* bei1 = (const float*)d_in[9];
  const float* Wm   = (const float*)d_in[10];
  const float* bm   = (const float*)d_in[11];
  const float* gm   = (const float*)d_in[12];
  const float* bem  = (const float*)d_in[13];
  const float* Wu   = (const float*)d_in[14];
  const float* bu   = (const float*)d_in[15];
  const float* gu   = (const float*)d_in[16];
  const float* beu  = (const float*)d_in[17];
  const float* Wf0  = (const float*)d_in[18];
  const float* bf0  = (const float*)d_in[19];
  const float* Wf1  = (const float*)d_in[20];
  const float* bf1  = (const float*)d_in[21];
  const float* Wf2  = (const float*)d_in[22];
  const float* bf2  = (const float*)d_in[23];
  const float* Wf3  = (const float*)d_in[24];
  const float* bf3  = (const float*)d_in[25];
  const float* Wo   = (const float*)d_in[26];
  const float* bo   = (const float*)d_in[27];
  const int* src = col;
  const int* dst = col + EE;

  // CSR build + single-launch weight pre-split
  k_zero_stats<<<440,256>>>();
  k_count<<<(EE+255)/256,256>>>(dst);
  k_wsplit<<<(51200+255)/256,256>>>(Wf0, Wf1, Wf2, Wf3);
  k_scan<<<1,1024>>>();
  k_fill<<<(EE+255)/256,256>>>(src, dst);

  // init MLP
  k_init0<<<1184,256>>>(x, Wi0, bi0);
  k_finalize<<<1,32>>>(0, gi0, bei0);
  k_gemm2<32,true,1><<<296,256>>>(0, Wi1, bi1, /*preslot*/0, /*outslot*/1);
  k_finalize<<<1,32>>>(1, gi1, bei1);
  k_actstore<<<1184,256>>>(1, -1, 0);                    // feats[0]

  for (int i = 0; i < 10; i++){
    int sm = 2 + 2*i, su = 3 + 2*i;
    // msg GEMM -> fp16 rows
    k_gemm2<32,false,2><<<296,256>>>(i, Wm + i*1024, bm + i*32, -1, sm);
    k_finalize<<<1,32>>>(sm, gm + i*32, bem + i*32);
    k_gather<<<(NN*32+255)/256,256>>>(sm);
    k_gemm2<64,false,1><<<296,256>>>(i, Wu + i*2048, bu + i*32, -1, su);
    k_finalize<<<1,32>>>(su, gu + i*32, beu + i*32);
    k_actstore<<<1184,256>>>(su, (i >= 2) ? (i-2) : -1, i+1);
  }

  // final MLP on mma.sync tf32 (3xTF32, pre-split weights), head fused into L3
  const int MB = (NN + 127)/128;  // 782
  dim3 g0(MB, 4); k_fmma<0,false><<<g0,256>>>(bf0, (const float*)0, (const float*)0, (float*)0);
  dim3 g1(MB, 2); k_fmma<1,false><<<g1,256>>>(bf1, (const float*)0, (const float*)0, (float*)0);
  dim3 g2(MB, 1); k_fmma<2,false><<<g2,256>>>(bf2, (const float*)0, (const float*)0, (float*)0);
  dim3 g3(MB, 1); k_fmma<3,true ><<<g3,256>>>(bf3, Wo, bo, (float*)d_out);
}

// round 13
// speedup vs baseline: 1.7591x; 1.7591x over previous
#include <cuda_runtime.h>
#include <math.h>
#include <stdint.h>

#define NN 100000
#define EE 1600000
#define NW (NN*32)

// ---------------- device scratch (static, no allocation) ----------------
__device__ __align__(16) float g_feats[11][NW];
__device__ __align__(16) float g_preA[NW];
__device__ __align__(16) float g_preB[NW];
__device__ __align__(16) float g_agg[NW];
__device__ float g_stats[22][64];
__device__ __align__(16) float g_scale[22][32];
__device__ __align__(16) float g_shift[22][32];
__device__ __align__(16) float g_h256[NN*256];
__device__ __align__(16) float g_h128[NN*128];
__device__ __align__(16) float g_h64[NN*64];
__device__ __align__(16) float g_h32[NW];
// CSR scratch
__device__ int g_deg[NN];
__device__ int g_cursor[NN];
__device__ int g_rowptr[NN+1];
__device__ int g_csrsrc[EE];
__device__ int g_psum[98];
__device__ int g_poff[98];

__device__ __forceinline__ float lrelu(float x){ return x > 0.f ? x : 0.01f*x; }

// ---------------- tf32 helpers (base ISA, sm_80+) ----------------
__device__ __forceinline__ uint32_t f2tf32(float x){
  uint32_t r; asm("cvt.rna.tf32.f32 %0, %1;" : "=r"(r) : "f"(x)); return r;
}
__device__ __forceinline__ void tf32_split(float x, uint32_t& hi, uint32_t& lo){
  uint32_t h = f2tf32(x);
  hi = h;
  lo = f2tf32(x - __uint_as_float(h));
}
__device__ __forceinline__ void mma_tf32(float* c, const uint32_t* a, const uint32_t* b){
  asm volatile("mma.sync.aligned.m16n8k8.row.col.f32.tf32.tf32.f32 "
    "{%0,%1,%2,%3}, {%4,%5,%6,%7}, {%8,%9}, {%0,%1,%2,%3};"
    : "+f"(c[0]), "+f"(c[1]), "+f"(c[2]), "+f"(c[3])
    : "r"(a[0]), "r"(a[1]), "r"(a[2]), "r"(a[3]), "r"(b[0]), "r"(b[1]));
}

// ---------------- zero kernels ----------------
__global__ void k_zero_stats(){
  int i = blockIdx.x*blockDim.x + threadIdx.x;
  if (i < 22*64) ((float*)g_stats)[i] = 0.f;
  int stride = gridDim.x*blockDim.x;
  for (int j = i; j < NN; j += stride) g_deg[j] = 0;
}

// ---------------- CSR build ----------------
__global__ void k_count(const int* __restrict__ dst){
  int i = blockIdx.x*blockDim.x + threadIdx.x;
  if (i < EE) atomicAdd(&g_deg[dst[i]], 1);
}

// phase 1: per-block (1024-elem chunk) degree sums
__global__ void k_scan1(){
  __shared__ int sh[1024];
  int b = blockIdx.x, t = threadIdx.x;
  int i = b*1024 + t;
  int v = (i < NN) ? g_deg[i] : 0;
  sh[t] = v; __syncthreads();
  for (int off = 512; off > 0; off >>= 1){
    if (t < off) sh[t] += sh[t + off];
    __syncthreads();
  }
  if (t == 0) g_psum[b] = sh[0];
}

// phase 2: exclusive scan of the 98 partials (one tiny block)
__global__ void k_scan2(){
  __shared__ int sh[128];
  int t = threadIdx.x;
  int v = (t < 98) ? g_psum[t] : 0;
  sh[t] = v; __syncthreads();
  for (int off = 1; off < 128; off <<= 1){
    int x = sh[t];
    int a = (t >= off) ? sh[t - off] : 0;
    __syncthreads();
    sh[t] = x + a;
    __syncthreads();
  }
  if (t < 98) g_poff[t] = (t > 0) ? sh[t-1] : 0;
}

// phase 3: per-chunk inclusive scan + chunk offset -> rowptr/cursor
__global__ void k_scan3(){
  __shared__ int sh[1024];
  int b = blockIdx.x, t = threadIdx.x;
  int i = b*1024 + t;
  int v = (i < NN) ? g_deg[i] : 0;
  sh[t] = v; __syncthreads();
  for (int off = 1; off < 1024; off <<= 1){
    int x = sh[t];
    int a = (t >= off) ? sh[t - off] : 0;
    __syncthreads();
    sh[t] = x + a;
    __syncthreads();
  }
  int excl = sh[t] - v + g_poff[b];
  if (i < NN){
    g_rowptr[i] = excl;
    g_cursor[i] = excl;
    if (i == NN-1) g_rowptr[NN] = excl + v;
  }
}

__global__ void k_fill(const int* __restrict__ src, const int* __restrict__ dst){
  int i = blockIdx.x*blockDim.x + threadIdx.x;
  if (i >= EE) return;
  int d = dst[i];
  int p = atomicAdd(&g_cursor[d], 1);
  g_csrsrc[p] = src[i];
}

// ---------------- per-block column-stat commit ----------------
__device__ __forceinline__ void stats_commit(float s, float sq, int slot){
  __shared__ float red[2][8][32];
  int c = threadIdx.x & 31, w = threadIdx.x >> 5;
  red[0][w][c] = s; red[1][w][c] = sq;
  __syncthreads();
  if (w == 0){
    float a = 0.f, b = 0.f;
#pragma unroll
    for (int j = 0; j < 8; j++){ a += red[0][j][c]; b += red[1][j][c]; }
    atomicAdd(&g_stats[slot][c],    a);
    atomicAdd(&g_stats[slot][32+c], b);
  }
}

// ---------------- init layer 0 ----------------
__global__ void k_init0(const float* __restrict__ x, const float* __restrict__ W0,
                        const float* __restrict__ b0){
  int c = threadIdx.x & 31;
  float wc = W0[c], bc = b0[c];
  float s = 0.f, sq = 0.f;
  int stride = gridDim.x*blockDim.x;
  for (int idx = blockIdx.x*blockDim.x + threadIdx.x; idx < NW; idx += stride){
    float v = fmaf(x[idx >> 5], wc, bc);
    g_preA[idx] = v; s += v; sq += v*v;
  }
  stats_commit(s, sq, 0);
}

// ---------------- finalize BN stats into fused scale/shift ----------------
__global__ void k_finalize(int slot, const float* __restrict__ g,
                           const float* __restrict__ be){
  int c = threadIdx.x;
  float m = g_stats[slot][c] * (1.f/NN);
  float v = g_stats[slot][32+c] * (1.f/NN) - m*m;
  float istd = rsqrtf(v + 1e-5f);
  float sc = g[c]*istd;
  g_scale[slot][c] = sc;
  g_shift[slot][c] = fmaf(-m, sc, be[c]);
}

// ---------------- register-weight small GEMM --------------------------------------
template<int K, bool PRE>
__global__ void __launch_bounds__(256) k_gemm2(int fidx, const float* __restrict__ Wg,
        const float* __restrict__ bias, int outsel, int preslot, int outslot)
{
  __shared__ __align__(16) float in_sh[8][4][K];
  const float* in1 = PRE ? g_preA : g_feats[fidx];
  float* out = outsel ? g_preB : g_preA;
  int lane = threadIdx.x & 31, w = threadIdx.x >> 5;
  float wreg[K];
#pragma unroll
  for (int k = 0; k < K; k++) wreg[k] = Wg[k*32 + lane];
  float b = bias[lane];
  float psc = 0.f, psh = 0.f;
  if (PRE){ psc = g_scale[preslot][lane]; psh = g_shift[preslot][lane]; }
  float s = 0.f, sq = 0.f;
  int gwarp  = blockIdx.x*8 + w;
  int nwarps = gridDim.x*8;
  for (int grp = gwarp; grp < NN/4; grp += nwarps){
    int r0 = grp*4;
#pragma unroll
    for (int j = 0; j < 4; j++){
      float v = in1[(r0+j)*32 + lane];
      if (PRE) v = lrelu(fmaf(v, psc, psh));
      in_sh[w][j][lane] = v;
      if (K == 64) in_sh[w][j][32 + lane] = g_agg[(r0+j)*32 + lane];
    }
    __syncwarp();
    float a0=b, a1=b, a2=b, a3=b;
#pragma unroll
    for (int k = 0; k < K; k += 4){
      float4 x0 = *(const float4*)&in_sh[w][0][k];
      float4 x1 = *(const float4*)&in_sh[w][1][k];
      float4 x2 = *(const float4*)&in_sh[w][2][k];
      float4 x3 = *(const float4*)&in_sh[w][3][k];
      a0 = fmaf(x0.x,wreg[k],a0); a0 = fmaf(x0.y,wreg[k+1],a0);
      a0 = fmaf(x0.z,wreg[k+2],a0); a0 = fmaf(x0.w,wreg[k+3],a0);
      a1 = fmaf(x1.x,wreg[k],a1); a1 = fmaf(x1.y,wreg[k+1],a1);
      a1 = fmaf(x1.z,wreg[k+2],a1); a1 = fmaf(x1.w,wreg[k+3],a1);
      a2 = fmaf(x2.x,wreg[k],a2); a2 = fmaf(x2.y,wreg[k+1],a2);
      a2 = fmaf(x2.z,wreg[k+2],a2); a2 = fmaf(x2.w,wreg[k+3],a2);
      a3 = fmaf(x3.x,wreg[k],a3); a3 = fmaf(x3.y,wreg[k+1],a3);
      a3 = fmaf(x3.z,wreg[k+2],a3); a3 = fmaf(x3.w,wreg[k+3],a3);
    }
    __syncwarp();
    out[(r0+0)*32+lane] = a0;
    out[(r0+1)*32+lane] = a1;
    out[(r0+2)*32+lane] = a2;
    out[(r0+3)*32+lane] = a3;
    s  += a0+a1+a2+a3;
    sq += a0*a0+a1*a1+a2*a2+a3*a3;
  }
  stats_commit(s, sq, outslot);
}

// ---------------- CSR pull-gather (ILP-8) ----------------
__global__ void __launch_bounds__(256) k_gather(int slot){
  int warp = (blockIdx.x*blockDim.x + threadIdx.x) >> 5;
  int lane = threadIdx.x & 31;
  if (warp >= NN) return;
  float sc = g_scale[slot][lane], sh = g_shift[slot][lane];
  int beg = g_rowptr[warp], end = g_rowptr[warp+1];
  float acc = 0.f;
  for (int base = beg; base < end; base += 32){
    int idx = base + lane;
    int s_l = (idx < end) ? g_csrsrc[idx] : 0;
    int nb = min(32, end - base);
    int j = 0;
    for (; j + 8 <= nb; j += 8){
      int s0 = __shfl_sync(0xffffffffu, s_l, j);
      int s1 = __shfl_sync(0xffffffffu, s_l, j+1);
      int s2 = __shfl_sync(0xffffffffu, s_l, j+2);
      int s3 = __shfl_sync(0xffffffffu, s_l, j+3);
      int s4 = __shfl_sync(0xffffffffu, s_l, j+4);
      int s5 = __shfl_sync(0xffffffffu, s_l, j+5);
      int s6 = __shfl_sync(0xffffffffu, s_l, j+6);
      int s7 = __shfl_sync(0xffffffffu, s_l, j+7);
      float v0 = g_preA[s0*32 + lane];
      float v1 = g_preA[s1*32 + lane];
      float v2 = g_preA[s2*32 + lane];
      float v3 = g_preA[s3*32 + lane];
      float v4 = g_preA[s4*32 + lane];
      float v5 = g_preA[s5*32 + lane];
      float v6 = g_preA[s6*32 + lane];
      float v7 = g_preA[s7*32 + lane];
      acc += lrelu(fmaf(v0, sc, sh));
      acc += lrelu(fmaf(v1, sc, sh));
      acc += lrelu(fmaf(v2, sc, sh));
      acc += lrelu(fmaf(v3, sc, sh));
      acc += lrelu(fmaf(v4, sc, sh));
      acc += lrelu(fmaf(v5, sc, sh));
      acc += lrelu(fmaf(v6, sc, sh));
      acc += lrelu(fmaf(v7, sc, sh));
    }
    for (; j < nb; j++){
      int ss = __shfl_sync(0xffffffffu, s_l, j);
      acc += lrelu(fmaf(g_preA[ss*32 + lane], sc, sh));
    }
  }
  g_agg[warp*32 + lane] = acc;
}

// ---------------- apply BN+lrelu (+residual) ----------------
__global__ void k_actstore(int slot, int ridx, int oidx){
  int c = threadIdx.x & 31;
  float sc = g_scale[slot][c], sh = g_shift[slot][c];
  const float* resid = (ridx >= 0) ? g_feats[ridx] : (const float*)0;
  float* dstp = g_feats[oidx];
  int stride = gridDim.x*blockDim.x;
  for (int i = blockIdx.x*blockDim.x + threadIdx.x; i < NW; i += stride){
    float v = lrelu(fmaf(g_preB[i], sc, sh));
    if (ridx >= 0) v += resid[i];
    dstp[i] = v;
  }
}

// ---------------- final MLP via mma.sync tf32 (3xTF32) -----------------
template<int L> struct FC;
template<> struct FC<0>{ static constexpr int K=32,  C=256; };
template<> struct FC<1>{ static constexpr int K=256, C=128; };
template<> struct FC<2>{ static constexpr int K=128, C=64;  };
template<> struct FC<3>{ static constexpr int K=64,  C=32;  };

template<int L>
__global__ void __launch_bounds__(256) k_fmma(const float* __restrict__ Wg,
                                              const float* __restrict__ bias){
  constexpr int K = FC<L>::K, C = FC<L>::C;
  constexpr int NSUB = (C >= 64) ? 8 : C/8;
  const float* in = (L==0)? g_feats[10] : (L==1)? g_h256 : (L==2)? g_h128 : g_h64;
  float* out      = (L==0)? g_h256 : (L==1)? g_h128 : (L==2)? g_h64 : g_h32;
  int lane = threadIdx.x & 31, w = threadIdx.x >> 5;
  int rowW = blockIdx.x*128 + w*16;
  int colW = blockIdx.y*(NSUB*8);
  int g = lane >> 2, tig = lane & 3;
  int r0 = rowW + g, r1 = r0 + 8;

  float acc[NSUB][4];
#pragma unroll
  for (int s = 0; s < NSUB; s++){
    acc[s][0] = 0.f; acc[s][1] = 0.f; acc[s][2] = 0.f; acc[s][3] = 0.f;
  }

  const float* inA0 = in + (size_t)r0*K;
  const float* inA1 = in + (size_t)r1*K;
  bool v0 = (r0 < NN), v1 = (r1 < NN);

#pragma unroll 2
  for (int k0 = 0; k0 < K; k0 += 8){
    int ka = k0 + tig;
    float x0 = v0 ? inA0[ka]     : 0.f;
    float x1 = v1 ? inA1[ka]     : 0.f;
    float x2 = v0 ? inA0[ka + 4] : 0.f;
    float x3 = v1 ? inA1[ka + 4] : 0.f;
    uint32_t aH[4], aL[4];
    tf32_split(x0, aH[0], aL[0]);
    tf32_split(x1, aH[1], aL[1]);
    tf32_split(x2, aH[2], aL[2]);
    tf32_split(x3, aH[3], aL[3]);

    uint32_t bH[NSUB][2], bL[NSUB][2];
#pragma unroll
    for (int s = 0; s < NSUB; s++){
      int col = colW + s*8 + g;
      float w0 = Wg[(size_t)ka*C + col];
      float w1 = Wg[(size_t)(ka+4)*C + col];
      tf32_split(w0, bH[s][0], bL[s][0]);
      tf32_split(w1, bH[s][1], bL[s][1]);
    }
#pragma unroll
    for (int s = 0; s < NSUB; s++){
      mma_tf32(acc[s], aH, bH[s]);
      mma_tf32(acc[s], aH, bL[s]);
      mma_tf32(acc[s], aL, bH[s]);
    }
  }

#pragma unroll
  for (int s = 0; s < NSUB; s++){
    int c0 = colW + s*8 + 2*tig;
    float b0 = bias[c0], b1 = bias[c0+1];
    if (v0){
      out[(size_t)r0*C + c0]     = lrelu(acc[s][0] + b0);
      out[(size_t)r0*C + c0 + 1] = lrelu(acc[s][1] + b1);
    }
    if (v1){
      out[(size_t)r1*C + c0]     = lrelu(acc[s][2] + b0);
      out[(size_t)r1*C + c0 + 1] = lrelu(acc[s][3] + b1);
    }
  }
}

// ---------------- sigmoid head ----------------
__global__ void k_head(const float* __restrict__ Wo, const float* __restrict__ bo,
                       float* __restrict__ out){
  __shared__ float w[32];
  if (threadIdx.x < 32) w[threadIdx.x] = Wo[threadIdx.x];
  __syncthreads();
  int n = blockIdx.x*blockDim.x + threadIdx.x;
  if (n >= NN) return;
  const float4* hp = (const float4*)(g_h32 + n*32);
  const float4* wp = (const float4*)w;
  float z = bo[0];
#pragma unroll
  for (int q = 0; q < 8; q++){
    float4 a = hp[q]; float4 ww = wp[q];
    z += a.x*ww.x + a.y*ww.y + a.z*ww.z + a.w*ww.w;
  }
  out[n] = 1.f/(1.f + expf(-z));
}

// ---------------- launch ----------------
extern "C" void kernel_launch(void* const* d_in, const int* in_sizes, int n_in,
                              void* d_out, int out_size){
  const float* x    = (const float*)d_in[0];
  const int*   col  = (const int*)d_in[1];
  const float* Wi0  = (const float*)d_in[2];
  const float* bi0  = (const float*)d_in[3];
  const float* gi0  = (const float*)d_in[4];
  const float* bei0 = (const float*)d_in[5];
  const float* Wi1  = (const float*)d_in[6];
  const float* bi1  = (const float*)d_in[7];
  const float* gi1  = (const float*)d_in[8];
  const float* bei1 = (const float*)d_in[9];
  const float* Wm   = (const float*)d_in[10];
  const float* bm   = (const float*)d_in[11];
  const float* gm   = (const float*)d_in[12];
  const float* bem  = (const float*)d_in[13];
  const float* Wu   = (const float*)d_in[14];
  const float* bu   = (const float*)d_in[15];
  const float* gu   = (const float*)d_in[16];
  const float* beu  = (const float*)d_in[17];
  const float* Wf0  = (const float*)d_in[18];
  const float* bf0  = (const float*)d_in[19];
  const float* Wf1  = (const float*)d_in[20];
  const float* bf1  = (const float*)d_in[21];
  const float* Wf2  = (const float*)d_in[22];
  const float* bf2  = (const float*)d_in[23];
  const float* Wf3  = (const float*)d_in[24];
  const float* bf3  = (const float*)d_in[25];
  const float* Wo   = (const float*)d_in[26];
  const float* bo   = (const float*)d_in[27];
  const int* src = col;
  const int* dst = col + EE;

  // CSR build (parallel 3-phase scan)
  k_zero_stats<<<440,256>>>();
  k_count<<<(EE+255)/256,256>>>(dst);
  k_scan1<<<98,1024>>>();
  k_scan2<<<1,128>>>();
  k_scan3<<<98,1024>>>();
  k_fill<<<(EE+255)/256,256>>>(src, dst);

  // init MLP
  k_init0<<<1184,256>>>(x, Wi0, bi0);
  k_finalize<<<1,32>>>(0, gi0, bei0);
  k_gemm2<32,true><<<296,256>>>(0, Wi1, bi1, /*out=B*/1, /*preslot*/0, /*outslot*/1);
  k_finalize<<<1,32>>>(1, gi1, bei1);
  k_actstore<<<1184,256>>>(1, -1, 0);                    // feats[0]

  for (int i = 0; i < 10; i++){
    int sm = 2 + 2*i, su = 3 + 2*i;
    k_gemm2<32,false><<<296,256>>>(i, Wm + i*1024, bm + i*32, /*out=A*/0, -1, sm);
    k_finalize<<<1,32>>>(sm, gm + i*32, bem + i*32);
    k_gather<<<(NN*32+255)/256,256>>>(sm);
    k_gemm2<64,false><<<296,256>>>(i, Wu + i*2048, bu + i*32, /*out=B*/1, -1, su);
    k_finalize<<<1,32>>>(su, gu + i*32, beu + i*32);
    k_actstore<<<1184,256>>>(su, (i >= 2) ? (i-2) : -1, i+1);
  }

  // final MLP on mma.sync tf32 (3xTF32)
  const int MB = (NN + 127)/128;  // 782
  dim3 g0(MB, 4); k_fmma<0><<<g0,256>>>(Wf0, bf0);
  dim3 g1(MB, 2); k_fmma<1><<<g1,256>>>(Wf1, bf1);
  dim3 g2(MB, 1); k_fmma<2><<<g2,256>>>(Wf2, bf2);
  dim3 g3(MB, 1); k_fmma<3><<<g3,256>>>(Wf3, bf3);
  k_head<<<(NN+255)/256,256>>>(Wo, bo, (float*)d_out);
}

// round 15
// speedup vs baseline: 1.8241x; 1.0369x over previous
#include <cuda_runtime.h>
#include <math.h>
#include <stdint.h>

#define NN 100000
#define EE 1600000
#define NW (NN*32)

// ---------------- device scratch (static, no allocation) ----------------
__device__ __align__(16) float g_feats[11][NW];
__device__ __align__(16) float g_preA[NW];
__device__ __align__(16) float g_preB[NW];
__device__ __align__(16) float g_agg[NW];
__device__ float g_stats[22][64];
__device__ __align__(16) float g_scale[22][32];
__device__ __align__(16) float g_shift[22][32];
__device__ __align__(16) float g_h256[NN*256];
__device__ __align__(16) float g_h128[NN*128];
__device__ __align__(16) float g_h64[NN*64];
__device__ __align__(16) float g_h32[NW];
// CSR scratch
__device__ int g_deg[NN];
__device__ int g_cursor[NN];
__device__ int g_rowptr[NN+1];
__device__ int g_csrsrc[EE];
__device__ int g_psum[98];
__device__ int g_poff[98];

__device__ __forceinline__ float lrelu(float x){ return x > 0.f ? x : 0.01f*x; }

// fused BN scale/shift for column `lane`, straight from raw stats
__device__ __forceinline__ void bn_coef(int slot, int lane,
                                        const float* __restrict__ g,
                                        const float* __restrict__ be,
                                        float& sc, float& sh){
  float m = g_stats[slot][lane] * (1.f/NN);
  float v = g_stats[slot][32+lane] * (1.f/NN) - m*m;
  float istd = rsqrtf(v + 1e-5f);
  sc = g[lane]*istd;
  sh = fmaf(-m, sc, be[lane]);
}

// ---------------- tf32 helpers (base ISA, sm_80+) ----------------
__device__ __forceinline__ uint32_t f2tf32(float x){
  uint32_t r; asm("cvt.rna.tf32.f32 %0, %1;" : "=r"(r) : "f"(x)); return r;
}
__device__ __forceinline__ void tf32_split(float x, uint32_t& hi, uint32_t& lo){
  uint32_t h = f2tf32(x);
  hi = h;
  lo = f2tf32(x - __uint_as_float(h));
}
__device__ __forceinline__ void mma_tf32(float* c, const uint32_t* a, const uint32_t* b){
  asm volatile("mma.sync.aligned.m16n8k8.row.col.f32.tf32.tf32.f32 "
    "{%0,%1,%2,%3}, {%4,%5,%6,%7}, {%8,%9}, {%0,%1,%2,%3};"
    : "+f"(c[0]), "+f"(c[1]), "+f"(c[2]), "+f"(c[3])
    : "r"(a[0]), "r"(a[1]), "r"(a[2]), "r"(a[3]), "r"(b[0]), "r"(b[1]));
}

// ---------------- zero kernels ----------------
__global__ void k_zero_stats(){
  int i = blockIdx.x*blockDim.x + threadIdx.x;
  if (i < 22*64) ((float*)g_stats)[i] = 0.f;
  int stride = gridDim.x*blockDim.x;
  for (int j = i; j < NN; j += stride) g_deg[j] = 0;
}

// ---------------- CSR build ----------------
__global__ void k_count(const int* __restrict__ dst){
  int i = blockIdx.x*blockDim.x + threadIdx.x;
  if (i < EE) atomicAdd(&g_deg[dst[i]], 1);
}

__global__ void k_scan1(){
  __shared__ int sh[1024];
  int b = blockIdx.x, t = threadIdx.x;
  int i = b*1024 + t;
  int v = (i < NN) ? g_deg[i] : 0;
  sh[t] = v; __syncthreads();
  for (int off = 512; off > 0; off >>= 1){
    if (t < off) sh[t] += sh[t + off];
    __syncthreads();
  }
  if (t == 0) g_psum[b] = sh[0];
}

__global__ void k_scan2(){
  __shared__ int sh[128];
  int t = threadIdx.x;
  int v = (t < 98) ? g_psum[t] : 0;
  sh[t] = v; __syncthreads();
  for (int off = 1; off < 128; off <<= 1){
    int x = sh[t];
    int a = (t >= off) ? sh[t - off] : 0;
    __syncthreads();
    sh[t] = x + a;
    __syncthreads();
  }
  if (t < 98) g_poff[t] = (t > 0) ? sh[t-1] : 0;
}

__global__ void k_scan3(){
  __shared__ int sh[1024];
  int b = blockIdx.x, t = threadIdx.x;
  int i = b*1024 + t;
  int v = (i < NN) ? g_deg[i] : 0;
  sh[t] = v; __syncthreads();
  for (int off = 1; off < 1024; off <<= 1){
    int x = sh[t];
    int a = (t >= off) ? sh[t - off] : 0;
    __syncthreads();
    sh[t] = x + a;
    __syncthreads();
  }
  int excl = sh[t] - v + g_poff[b];
  if (i < NN){
    g_rowptr[i] = excl;
    g_cursor[i] = excl;
    if (i == NN-1) g_rowptr[NN] = excl + v;
  }
}

__global__ void k_fill(const int* __restrict__ src, const int* __restrict__ dst){
  int i = blockIdx.x*blockDim.x + threadIdx.x;
  if (i >= EE) return;
  int d = dst[i];
  int p = atomicAdd(&g_cursor[d], 1);
  g_csrsrc[p] = src[i];
}

// ---------------- per-block column-stat commit ----------------
__device__ __forceinline__ void stats_commit(float s, float sq, int slot){
  __shared__ float red[2][8][32];
  int c = threadIdx.x & 31, w = threadIdx.x >> 5;
  red[0][w][c] = s; red[1][w][c] = sq;
  __syncthreads();
  if (w == 0){
    float a = 0.f, b = 0.f;
#pragma unroll
    for (int j = 0; j < 8; j++){ a += red[0][j][c]; b += red[1][j][c]; }
    atomicAdd(&g_stats[slot][c],    a);
    atomicAdd(&g_stats[slot][32+c], b);
  }
}

// ---------------- init layer 0 ----------------
__global__ void k_init0(const float* __restrict__ x, const float* __restrict__ W0,
                        const float* __restrict__ b0){
  int c = threadIdx.x & 31;
  float wc = W0[c], bc = b0[c];
  float s = 0.f, sq = 0.f;
  int stride = gridDim.x*blockDim.x;
  for (int idx = blockIdx.x*blockDim.x + threadIdx.x; idx < NW; idx += stride){
    float v = fmaf(x[idx >> 5], wc, bc);
    g_preA[idx] = v; s += v; sq += v*v;
  }
  stats_commit(s, sq, 0);
}

// ---------------- finalize BN stats (gather slots only) ----------------
__global__ void k_finalize(int slot, const float* __restrict__ g,
                           const float* __restrict__ be){
  int c = threadIdx.x;
  float sc, sh;
  bn_coef(slot, c, g, be, sc, sh);
  g_scale[slot][c] = sc;
  g_shift[slot][c] = sh;
}

// ---------------- register-weight small GEMM --------------------------------------
// PRE: in = lrelu(bn(g_preA, preslot)) with coefs computed inline (block-level)
template<int K, bool PRE>
__global__ void __launch_bounds__(256) k_gemm2(int fidx, const float* __restrict__ Wg,
        const float* __restrict__ bias, int outsel, int preslot, int outslot,
        const float* __restrict__ pg, const float* __restrict__ pbe)
{
  __shared__ __align__(16) float in_sh[8][4][K];
  const float* in1 = PRE ? g_preA : g_feats[fidx];
  float* out = outsel ? g_preB : g_preA;
  int lane = threadIdx.x & 31, w = threadIdx.x >> 5;
  float wreg[K];
#pragma unroll
  for (int k = 0; k < K; k++) wreg[k] = Wg[k*32 + lane];
  float b = bias[lane];
  float psc = 0.f, psh = 0.f;
  if (PRE) bn_coef(preslot, lane, pg, pbe, psc, psh);
  float s = 0.f, sq = 0.f;
  int gwarp  = blockIdx.x*8 + w;
  int nwarps = gridDim.x*8;
  for (int grp = gwarp; grp < NN/4; grp += nwarps){
    int r0 = grp*4;
#pragma unroll
    for (int j = 0; j < 4; j++){
      float v = in1[(r0+j)*32 + lane];
      if (PRE) v = lrelu(fmaf(v, psc, psh));
      in_sh[w][j][lane] = v;
      if (K == 64) in_sh[w][j][32 + lane] = g_agg[(r0+j)*32 + lane];
    }
    __syncwarp();
    float a0=b, a1=b, a2=b, a3=b;
#pragma unroll
    for (int k = 0; k < K; k += 4){
      float4 x0 = *(const float4*)&in_sh[w][0][k];
      float4 x1 = *(const float4*)&in_sh[w][1][k];
      float4 x2 = *(const float4*)&in_sh[w][2][k];
      float4 x3 = *(const float4*)&in_sh[w][3][k];
      a0 = fmaf(x0.x,wreg[k],a0); a0 = fmaf(x0.y,wreg[k+1],a0);
      a0 = fmaf(x0.z,wreg[k+2],a0); a0 = fmaf(x0.w,wreg[k+3],a0);
      a1 = fmaf(x1.x,wreg[k],a1); a1 = fmaf(x1.y,wreg[k+1],a1);
      a1 = fmaf(x1.z,wreg[k+2],a1); a1 = fmaf(x1.w,wreg[k+3],a1);
      a2 = fmaf(x2.x,wreg[k],a2); a2 = fmaf(x2.y,wreg[k+1],a2);
      a2 = fmaf(x2.z,wreg[k+2],a2); a2 = fmaf(x2.w,wreg[k+3],a2);
      a3 = fmaf(x3.x,wreg[k],a3); a3 = fmaf(x3.y,wreg[k+1],a3);
      a3 = fmaf(x3.z,wreg[k+2],a3); a3 = fmaf(x3.w,wreg[k+3],a3);
    }
    __syncwarp();
    out[(r0+0)*32+lane] = a0;
    out[(r0+1)*32+lane] = a1;
    out[(r0+2)*32+lane] = a2;
    out[(r0+3)*32+lane] = a3;
    s  += a0+a1+a2+a3;
    sq += a0*a0+a1*a1+a2*a2+a3*a3;
  }
  stats_commit(s, sq, outslot);
}

// ---------------- CSR pull-gather (ILP-8, table-based coefs) ----------------
__global__ void __launch_bounds__(256) k_gather(int slot){
  int warp = (blockIdx.x*blockDim.x + threadIdx.x) >> 5;
  int lane = threadIdx.x & 31;
  if (warp >= NN) return;
  float sc = g_scale[slot][lane], sh = g_shift[slot][lane];
  int beg = g_rowptr[warp], end = g_rowptr[warp+1];
  float acc = 0.f;
  for (int base = beg; base < end; base += 32){
    int idx = base + lane;
    int s_l = (idx < end) ? g_csrsrc[idx] : 0;
    int nb = min(32, end - base);
    int j = 0;
    for (; j + 8 <= nb; j += 8){
      int s0 = __shfl_sync(0xffffffffu, s_l, j);
      int s1 = __shfl_sync(0xffffffffu, s_l, j+1);
      int s2 = __shfl_sync(0xffffffffu, s_l, j+2);
      int s3 = __shfl_sync(0xffffffffu, s_l, j+3);
      int s4 = __shfl_sync(0xffffffffu, s_l, j+4);
      int s5 = __shfl_sync(0xffffffffu, s_l, j+5);
      int s6 = __shfl_sync(0xffffffffu, s_l, j+6);
      int s7 = __shfl_sync(0xffffffffu, s_l, j+7);
      float v0 = g_preA[s0*32 + lane];
      float v1 = g_preA[s1*32 + lane];
      float v2 = g_preA[s2*32 + lane];
      float v3 = g_preA[s3*32 + lane];
      float v4 = g_preA[s4*32 + lane];
      float v5 = g_preA[s5*32 + lane];
      float v6 = g_preA[s6*32 + lane];
      float v7 = g_preA[s7*32 + lane];
      acc += lrelu(fmaf(v0, sc, sh));
      acc += lrelu(fmaf(v1, sc, sh));
      acc += lrelu(fmaf(v2, sc, sh));
      acc += lrelu(fmaf(v3, sc, sh));
      acc += lrelu(fmaf(v4, sc, sh));
      acc += lrelu(fmaf(v5, sc, sh));
      acc += lrelu(fmaf(v6, sc, sh));
      acc += lrelu(fmaf(v7, sc, sh));
    }
    for (; j < nb; j++){
      int ss = __shfl_sync(0xffffffffu, s_l, j);
      acc += lrelu(fmaf(g_preA[ss*32 + lane], sc, sh));
    }
  }
  g_agg[warp*32 + lane] = acc;
}

// ---------------- apply BN+lrelu (+residual), coefs inline (block-level) ----------
__global__ void k_actstore(int slot, int ridx, int oidx,
        const float* __restrict__ pg, const float* __restrict__ pbe){
  int c = threadIdx.x & 31;
  float sc, sh;
  bn_coef(slot, c, pg, pbe, sc, sh);
  const float* resid = (ridx >= 0) ? g_feats[ridx] : (const float*)0;
  float* dstp = g_feats[oidx];
  int stride = gridDim.x*blockDim.x;
  for (int i = blockIdx.x*blockDim.x + threadIdx.x; i < NW; i += stride){
    float v = lrelu(fmaf(g_preB[i], sc, sh));
    if (ridx >= 0) v += resid[i];
    dstp[i] = v;
  }
}

// ---------------- final MLP via mma.sync tf32 (3xTF32) -----------------
template<int L> struct FC;
template<> struct FC<0>{ static constexpr int K=32,  C=256; };
template<> struct FC<1>{ static constexpr int K=256, C=128; };
template<> struct FC<2>{ static constexpr int K=128, C=64;  };
template<> struct FC<3>{ static constexpr int K=64,  C=32;  };

template<int L>
__global__ void __launch_bounds__(256) k_fmma(const float* __restrict__ Wg,
                                              const float* __restrict__ bias){
  constexpr int K = FC<L>::K, C = FC<L>::C;
  constexpr int NSUB = (C >= 64) ? 8 : C/8;
  const float* in = (L==0)? g_feats[10] : (L==1)? g_h256 : (L==2)? g_h128 : g_h64;
  float* out      = (L==0)? g_h256 : (L==1)? g_h128 : (L==2)? g_h64 : g_h32;
  int lane = threadIdx.x & 31, w = threadIdx.x >> 5;
  int rowW = blockIdx.x*128 + w*16;
  int colW = blockIdx.y*(NSUB*8);
  int g = lane >> 2, tig = lane & 3;
  int r0 = rowW + g, r1 = r0 + 8;

  float acc[NSUB][4];
#pragma unroll
  for (int s = 0; s < NSUB; s++){
    acc[s][0] = 0.f; acc[s][1] = 0.f; acc[s][2] = 0.f; acc[s][3] = 0.f;
  }

  const float* inA0 = in + (size_t)r0*K;
  const float* inA1 = in + (size_t)r1*K;
  bool v0 = (r0 < NN), v1 = (r1 < NN);

#pragma unroll 2
  for (int k0 = 0; k0 < K; k0 += 8){
    int ka = k0 + tig;
    float x0 = v0 ? inA0[ka]     : 0.f;
    float x1 = v1 ? inA1[ka]     : 0.f;
    float x2 = v0 ? inA0[ka + 4] : 0.f;
    float x3 = v1 ? inA1[ka + 4] : 0.f;
    uint32_t aH[4], aL[4];
    tf32_split(x0, aH[0], aL[0]);
    tf32_split(x1, aH[1], aL[1]);
    tf32_split(x2, aH[2], aL[2]);
    tf32_split(x3, aH[3], aL[3]);

    uint32_t bH[NSUB][2], bL[NSUB][2];
#pragma unroll
    for (int s = 0; s < NSUB; s++){
      int col = colW + s*8 + g;
      float w0 = Wg[(size_t)ka*C + col];
      float w1 = Wg[(size_t)(ka+4)*C + col];
      tf32_split(w0, bH[s][0], bL[s][0]);
      tf32_split(w1, bH[s][1], bL[s][1]);
    }
#pragma unroll
    for (int s = 0; s < NSUB; s++){
      mma_tf32(acc[s], aH, bH[s]);
      mma_tf32(acc[s], aH, bL[s]);
      mma_tf32(acc[s], aL, bH[s]);
    }
  }

#pragma unroll
  for (int s = 0; s < NSUB; s++){
    int c0 = colW + s*8 + 2*tig;
    float b0 = bias[c0], b1 = bias[c0+1];
    if (v0){
      out[(size_t)r0*C + c0]     = lrelu(acc[s][0] + b0);
      out[(size_t)r0*C + c0 + 1] = lrelu(acc[s][1] + b1);
    }
    if (v1){
      out[(size_t)r1*C + c0]     = lrelu(acc[s][2] + b0);
      out[(size_t)r1*C + c0 + 1] = lrelu(acc[s][3] + b1);
    }
  }
}

// ---------------- sigmoid head ----------------
__global__ void k_head(const float* __restrict__ Wo, const float* __restrict__ bo,
                       float* __restrict__ out){
  __shared__ float w[32];
  if (threadIdx.x < 32) w[threadIdx.x] = Wo[threadIdx.x];
  __syncthreads();
  int n = blockIdx.x*blockDim.x + threadIdx.x;
  if (n >= NN) return;
  const float4* hp = (const float4*)(g_h32 + n*32);
  const float4* wp = (const float4*)w;
  float z = bo[0];
#pragma unroll
  for (int q = 0; q < 8; q++){
    float4 a = hp[q]; float4 ww = wp[q];
    z += a.x*ww.x + a.y*ww.y + a.z*ww.z + a.w*ww.w;
  }
  out[n] = 1.f/(1.f + expf(-z));
}

// ---------------- launch ----------------
extern "C" void kernel_launch(void* const* d_in, const int* in_sizes, int n_in,
                              void* d_out, int out_size){
  const float* x    = (const float*)d_in[0];
  const int*   col  = (const int*)d_in[1];
  const float* Wi0  = (const float*)d_in[2];
  const float* bi0  = (const float*)d_in[3];
  const float* gi0  = (const float*)d_in[4];
  const float* bei0 = (const float*)d_in[5];
  const float* Wi1  = (const float*)d_in[6];
  const float* bi1  = (const float*)d_in[7];
  const float* gi1  = (const float*)d_in[8];
  const float* bei1 = (const float*)d_in[9];
  const float* Wm   = (const float*)d_in[10];
  const float* bm   = (const float*)d_in[11];
  const float* gm   = (const float*)d_in[12];
  const float* bem  = (const float*)d_in[13];
  const float* Wu   = (const float*)d_in[14];
  const float* bu   = (const float*)d_in[15];
  const float* gu   = (const float*)d_in[16];
  const float* beu  = (const float*)d_in[17];
  const float* Wf0  = (const float*)d_in[18];
  const float* bf0  = (const float*)d_in[19];
  const float* Wf1  = (const float*)d_in[20];
  const float* bf1  = (const float*)d_in[21];
  const float* Wf2  = (const float*)d_in[22];
  const float* bf2  = (const float*)d_in[23];
  const float* Wf3  = (const float*)d_in[24];
  const float* bf3  = (const float*)d_in[25];
  const float* Wo   = (const float*)d_in[26];
  const float* bo   = (const float*)d_in[27];
  const int* src = col;
  const int* dst = col + EE;

  // one-time stream/event setup (first call is the uncaptured correctness run)
  static cudaStream_t s1 = 0;
  static cudaEvent_t evF = 0, evJ = 0;
  if (!s1){
    cudaStreamCreateWithFlags(&s1, cudaStreamNonBlocking);
    cudaEventCreateWithFlags(&evF, cudaEventDisableTiming);
    cudaEventCreateWithFlags(&evJ, cudaEventDisableTiming);
  }

  // zero (both branches depend on it)
  k_zero_stats<<<440,256>>>();
  cudaEventRecord(evF, 0);
  cudaStreamWaitEvent(s1, evF, 0);

  // CSR build on side stream (independent of init MLP)
  k_count<<<(EE+255)/256,256,0,s1>>>(dst);
  k_scan1<<<98,1024,0,s1>>>();
  k_scan2<<<1,128,0,s1>>>();
  k_scan3<<<98,1024,0,s1>>>();
  k_fill<<<(EE+255)/256,256,0,s1>>>(src, dst);
  cudaEventRecord(evJ, s1);

  // init MLP on main stream (coefs inline; no finalize launches here)
  k_init0<<<1184,256>>>(x, Wi0, bi0);
  k_gemm2<32,true><<<296,256>>>(0, Wi1, bi1, /*out=B*/1, /*preslot*/0, /*outslot*/1,
                                gi0, bei0);
  k_actstore<<<1184,256>>>(1, -1, 0, gi1, bei1);          // feats[0]

  // join: first gather needs the CSR
  cudaStreamWaitEvent(0, evJ, 0);

  for (int i = 0; i < 10; i++){
    int sm = 2 + 2*i, su = 3 + 2*i;
    k_gemm2<32,false><<<296,256>>>(i, Wm + i*1024, bm + i*32, /*out=A*/0, -1, sm,
                                   (const float*)0, (const float*)0);
    k_finalize<<<1,32>>>(sm, gm + i*32, bem + i*32);      // gather coefs (table)
    k_gather<<<(NN*32+255)/256,256>>>(sm);
    k_gemm2<64,false><<<296,256>>>(i, Wu + i*2048, bu + i*32, /*out=B*/1, -1, su,
                                   (const float*)0, (const float*)0);
    k_actstore<<<1184,256>>>(su, (i >= 2) ? (i-2) : -1, i+1, gu + i*32, beu + i*32);
  }

  // final MLP on mma.sync tf32 (3xTF32)
  const int MB = (NN + 127)/128;  // 782
  dim3 g0(MB, 4); k_fmma<0><<<g0,256>>>(Wf0, bf0);
  dim3 g1(MB, 2); k_fmma<1><<<g1,256>>>(Wf1, bf1);
  dim3 g2(MB, 1); k_fmma<2><<<g2,256>>>(Wf2, bf2);
  dim3 g3(MB, 1); k_fmma<3><<<g3,256>>>(Wf3, bf3);
  k_head<<<(NN+255)/256,256>>>(Wo, bo, (float*)d_out);
}